// round 15
// baseline (speedup 1.0000x reference)
#include <cuda_runtime.h>
#include <cuda_fp16.h>
#include <cstdint>

// LightGCN_2: N=100000 nodes, D=128 channels, E=1600000 edges
#define NN 100000
#define DD 128
#define EE 1600000
#define RATE 0.1f
#define INV_KEEP (1.0f / 0.9f)

#define SCAN_BLK 1024
#define SCAN_GRID ((NN + SCAN_BLK - 1) / SCAN_BLK)   // 98

// ---------------------------------------------------------------------------
// Static device scratch (allocation-free rule: __device__ globals)
// ---------------------------------------------------------------------------
__device__ __align__(16) float  g_h0[NN * DD];      // h0 = emb[x]     (fp32)
__device__ __align__(16) float  g_h1[NN * DD];      // layer-1 output  (fp32)
__device__ __align__(16) __half g_ga[NN * DD];      // dropout(h0,u1)  (fp16)
__device__ __align__(16) __half g_gb[NN * DD];      // dropout(h1,u2)  (fp16)

__device__ __align__(8)  uint2 g_cv[EE];            // CSR payload {col, val bits}
__device__ int g_rank[EE];                          // arrival rank within row
__device__ int g_cnt[NN];                           // row histogram
__device__ int g_rowptr[NN + 1];                    // CSR row pointers
__device__ unsigned long long g_scanstate[SCAN_GRID]; // lookback: hi32=ready, lo32=total

// ---------------------------------------------------------------------------
// K1: h0 = emb[x]; g_a = half(dropout(h0,u1)); also resets cnt + scan state.
// ---------------------------------------------------------------------------
__global__ void embed_dropout_kernel(const int* __restrict__ x,
                                     const float* __restrict__ emb,
                                     const float* __restrict__ u1) {
    int t = blockIdx.x * blockDim.x + threadIdx.x;   // over N*32
    if (t < NN) g_cnt[t] = 0;
    if (t < SCAN_GRID) g_scanstate[t] = 0ull;
    if (t >= NN * (DD / 4)) return;
    int i = t >> 5;
    int q = t & 31;
    int xi = x[i];
    float4 h = reinterpret_cast<const float4*>(emb + (size_t)xi * DD)[q];
    float4 u = reinterpret_cast<const float4*>(u1)[t];
    float gx = (u.x >= RATE) ? h.x * INV_KEEP : 0.f;
    float gy = (u.y >= RATE) ? h.y * INV_KEEP : 0.f;
    float gz = (u.z >= RATE) ? h.z * INV_KEEP : 0.f;
    float gw = (u.w >= RATE) ? h.w * INV_KEEP : 0.f;
    reinterpret_cast<float4*>(g_h0)[t] = h;
    __half2 p0 = __floats2half2_rn(gx, gy);
    __half2 p1 = __floats2half2_rn(gz, gw);
    uint2 packed = make_uint2(*reinterpret_cast<unsigned*>(&p0),
                              *reinterpret_cast<unsigned*>(&p1));
    reinterpret_cast<uint2*>(g_ga)[t] = packed;
}

// ---------------------------------------------------------------------------
// K2: histogram + per-edge arrival rank (single atomic pass)
// ---------------------------------------------------------------------------
__global__ void hist_rank_kernel(const int* __restrict__ rows) {
    int e = blockIdx.x * blockDim.x + threadIdx.x;
    if (e >= EE) return;
    g_rank[e] = atomicAdd(&g_cnt[rows[e]], 1);
}

// ---------------------------------------------------------------------------
// K3: single-pass exclusive scan of g_cnt -> g_rowptr (decoupled lookback).
// 98 blocks, all co-resident on 148 SMs -> spin-wait is deadlock-free.
// ---------------------------------------------------------------------------
__global__ void scan_lookback_kernel() {
    __shared__ int s[SCAN_BLK];
    __shared__ int base_sh;
    int tid = threadIdx.x;
    int b = blockIdx.x;
    int i = b * SCAN_BLK + tid;
    int v = (i < NN) ? g_cnt[i] : 0;
    s[tid] = v;
    __syncthreads();
#pragma unroll
    for (int off = 1; off < SCAN_BLK; off <<= 1) {
        int add = (tid >= off) ? s[tid - off] : 0;
        __syncthreads();
        s[tid] += add;
        __syncthreads();
    }
    // publish this block's total (ready bit + value in one 64-bit word)
    if (tid == 0) {
        unsigned long long st = (1ull << 32) | (unsigned)s[SCAN_BLK - 1];
        atomicExch(&g_scanstate[b], st);
    }
    // lookback: warp-parallel poll of all predecessor totals
    if (tid < 32) {
        int base = 0;
        for (int p = tid; p < b; p += 32) {
            unsigned long long st;
            do {
                st = *(volatile unsigned long long*)&g_scanstate[p];
            } while (!(st >> 32));
            base += (int)(st & 0xffffffffu);
        }
#pragma unroll
        for (int o = 16; o; o >>= 1)
            base += __shfl_down_sync(0xffffffffu, base, o);
        if (tid == 0) base_sh = base;
    }
    __syncthreads();
    if (i < NN) g_rowptr[i] = base_sh + s[tid] - v;   // exclusive
    if (i == 0) g_rowptr[NN] = EE;
}

// ---------------------------------------------------------------------------
// K4: scatter edges into CSR order (no atomics: rowptr + precomputed rank)
// ---------------------------------------------------------------------------
__global__ void scatter_kernel(const int* __restrict__ rows,
                               const int* __restrict__ cols,
                               const float* __restrict__ vals) {
    int e = blockIdx.x * blockDim.x + threadIdx.x;
    if (e >= EE) return;
    int pos = g_rowptr[rows[e]] + g_rank[e];
    g_cv[pos] = make_uint2((unsigned)cols[e], __float_as_uint(vals[e]));
}

// ---------------------------------------------------------------------------
// K5/K6: CSR SpMM, warp per row. Edge metadata via warp-uniform broadcast
// loads (no shfl), 8 gathers in flight, fp16 gathers, fp32 accumulation.
//   MODE 0: gather g_a; write h1 (fp32) AND g_b = half(dropout(h1,u2))
//   MODE 1: gather g_b; write out = (h0 + h1 + acc) / 3
// ---------------------------------------------------------------------------
__device__ __forceinline__ void fma_h4(float4& acc, float v, uint2 m) {
    __half2 p0 = *reinterpret_cast<__half2*>(&m.x);
    __half2 p1 = *reinterpret_cast<__half2*>(&m.y);
    float2 f0 = __half22float2(p0);
    float2 f1 = __half22float2(p1);
    acc.x += v * f0.x; acc.y += v * f0.y;
    acc.z += v * f1.x; acc.w += v * f1.y;
}

template <int MODE>
__global__ void spmm_csr_kernel(const float* __restrict__ u2,
                                float* __restrict__ out) {
    int gw   = (blockIdx.x * blockDim.x + threadIdx.x) >> 5;  // row
    int lane = threadIdx.x & 31;
    if (gw >= NN) return;

    int s = g_rowptr[gw];
    int e = g_rowptr[gw + 1];
    const uint2* __restrict__ cvp = g_cv;
    const uint2* __restrict__ gsrc =
        reinterpret_cast<const uint2*>(MODE == 0 ? g_ga : g_gb);

    float4 acc = make_float4(0.f, 0.f, 0.f, 0.f);

    int j = s;
    for (; j + 8 <= e; j += 8) {
        uint2 cv[8];
#pragma unroll
        for (int k = 0; k < 8; k++) cv[k] = cvp[j + k];      // uniform bcast
        uint2 m[8];
#pragma unroll
        for (int k = 0; k < 8; k++) m[k] = gsrc[(int)cv[k].x * 32 + lane];
#pragma unroll
        for (int k = 0; k < 8; k++)
            fma_h4(acc, __uint_as_float(cv[k].y), m[k]);
    }
    if (j + 4 <= e) {
        uint2 cv[4];
#pragma unroll
        for (int k = 0; k < 4; k++) cv[k] = cvp[j + k];
        uint2 m[4];
#pragma unroll
        for (int k = 0; k < 4; k++) m[k] = gsrc[(int)cv[k].x * 32 + lane];
#pragma unroll
        for (int k = 0; k < 4; k++)
            fma_h4(acc, __uint_as_float(cv[k].y), m[k]);
        j += 4;
    }
    for (; j < e; j++) {
        uint2 c = cvp[j];
        uint2 m = gsrc[(int)c.x * 32 + lane];
        fma_h4(acc, __uint_as_float(c.y), m);
    }

    int t = gw * 32 + lane;
    if (MODE == 0) {
        reinterpret_cast<float4*>(g_h1)[t] = acc;
        float4 u = reinterpret_cast<const float4*>(u2)[t];
        float gx  = (u.x >= RATE) ? acc.x * INV_KEEP : 0.f;
        float gy  = (u.y >= RATE) ? acc.y * INV_KEEP : 0.f;
        float gz  = (u.z >= RATE) ? acc.z * INV_KEEP : 0.f;
        float gw4 = (u.w >= RATE) ? acc.w * INV_KEEP : 0.f;
        __half2 p0 = __floats2half2_rn(gx, gy);
        __half2 p1 = __floats2half2_rn(gz, gw4);
        uint2 packed = make_uint2(*reinterpret_cast<unsigned*>(&p0),
                                  *reinterpret_cast<unsigned*>(&p1));
        reinterpret_cast<uint2*>(g_gb)[t] = packed;
    } else {
        float4 a = reinterpret_cast<const float4*>(g_h0)[t];
        float4 b = reinterpret_cast<const float4*>(g_h1)[t];
        const float kk = 1.0f / 3.0f;
        float4 o;
        o.x = (a.x + b.x + acc.x) * kk;
        o.y = (a.y + b.y + acc.y) * kk;
        o.z = (a.z + b.z + acc.z) * kk;
        o.w = (a.w + b.w + acc.w) * kk;
        reinterpret_cast<float4*>(out)[t] = o;
    }
}

// ---------------------------------------------------------------------------
// kernel_launch — graph-capturable pipeline (6 launches)
// inputs: 0:x(int32)[N] 1:rows[E] 2:cols[E] 3:A_vals[E] 4:emb[N*D] 5:u1 6:u2
// ---------------------------------------------------------------------------
extern "C" void kernel_launch(void* const* d_in, const int* in_sizes, int n_in,
                              void* d_out, int out_size) {
    const int*   x    = (const int*)  d_in[0];
    const int*   rows = (const int*)  d_in[1];
    const int*   cols = (const int*)  d_in[2];
    const float* vals = (const float*)d_in[3];
    const float* emb  = (const float*)d_in[4];
    const float* u1   = (const float*)d_in[5];
    const float* u2   = (const float*)d_in[6];
    float* out = (float*)d_out;

    const int TPB = 256;
    const int nd4_blocks  = (NN * (DD / 4) + TPB - 1) / TPB;  // 12500
    const int e_blocks    = (EE + TPB - 1) / TPB;             // 6250
    const int spmm_blocks = (NN * 32 + TPB - 1) / TPB;        // 12500

    embed_dropout_kernel<<<nd4_blocks, TPB>>>(x, emb, u1);    // + cnt/state reset
    hist_rank_kernel<<<e_blocks, TPB>>>(rows);
    scan_lookback_kernel<<<SCAN_GRID, SCAN_BLK>>>();
    scatter_kernel<<<e_blocks, TPB>>>(rows, cols, vals);

    spmm_csr_kernel<0><<<spmm_blocks, TPB>>>(u2, out);
    spmm_csr_kernel<1><<<spmm_blocks, TPB>>>(u2, out);
}

// round 16
// speedup vs baseline: 1.0090x; 1.0090x over previous
#include <cuda_runtime.h>
#include <cuda_fp16.h>
#include <cstdint>

// LightGCN_2: N=100000 nodes, D=128 channels, E=1600000 edges
#define NN 100000
#define DD 128
#define EE 1600000
#define RATE 0.1f
#define INV_KEEP (1.0f / 0.9f)

#define SCAN_BLK 1024
#define SCAN_GRID ((NN + SCAN_BLK - 1) / SCAN_BLK)   // 98

// ---------------------------------------------------------------------------
// Static device scratch (allocation-free rule: __device__ globals)
// ---------------------------------------------------------------------------
__device__ __align__(16) float  g_h1[NN * DD];      // layer-1 output  (fp32) [kept for clarity; unused]
__device__ __align__(16) __half g_ga[NN * DD];      // dropout(h0,u1)  (fp16)
__device__ __align__(16) __half g_gb[NN * DD];      // dropout(h1,u2)  (fp16)

__device__ __align__(16) uint2 g_cv[EE];            // CSR payload {col, val bits}
__device__ __align__(16) int g_rank[EE];            // arrival rank within row
__device__ int g_cnt[NN];                           // row histogram
__device__ int g_rowptr[NN + 1];                    // CSR row pointers
__device__ unsigned long long g_scanstate[SCAN_GRID]; // lookback: hi32=ready, lo32=total

// ---------------------------------------------------------------------------
// K1: g_a = half(dropout(emb[x], u1)); also resets cnt + scan state.
// (h0 is NOT materialized — SpMM-0's epilogue re-reads emb directly.)
// ---------------------------------------------------------------------------
__global__ void embed_dropout_kernel(const int* __restrict__ x,
                                     const float* __restrict__ emb,
                                     const float* __restrict__ u1) {
    int t = blockIdx.x * blockDim.x + threadIdx.x;   // over N*32
    if (t < NN) g_cnt[t] = 0;
    if (t < SCAN_GRID) g_scanstate[t] = 0ull;
    if (t >= NN * (DD / 4)) return;
    int i = t >> 5;
    int q = t & 31;
    int xi = x[i];
    float4 h = reinterpret_cast<const float4*>(emb + (size_t)xi * DD)[q];
    float4 u = reinterpret_cast<const float4*>(u1)[t];
    float gx = (u.x >= RATE) ? h.x * INV_KEEP : 0.f;
    float gy = (u.y >= RATE) ? h.y * INV_KEEP : 0.f;
    float gz = (u.z >= RATE) ? h.z * INV_KEEP : 0.f;
    float gw = (u.w >= RATE) ? h.w * INV_KEEP : 0.f;
    __half2 p0 = __floats2half2_rn(gx, gy);
    __half2 p1 = __floats2half2_rn(gz, gw);
    uint2 packed = make_uint2(*reinterpret_cast<unsigned*>(&p0),
                              *reinterpret_cast<unsigned*>(&p1));
    reinterpret_cast<uint2*>(g_ga)[t] = packed;
}

// ---------------------------------------------------------------------------
// K2: histogram + per-edge arrival rank.  4 edges/thread (MLP=4).
// ---------------------------------------------------------------------------
__global__ void hist_rank_kernel(const int* __restrict__ rows) {
    int t = blockIdx.x * blockDim.x + threadIdx.x;   // over EE/4
    if (t >= EE / 4) return;
    int4 r = reinterpret_cast<const int4*>(rows)[t];
    int4 rk;
    rk.x = atomicAdd(&g_cnt[r.x], 1);
    rk.y = atomicAdd(&g_cnt[r.y], 1);
    rk.z = atomicAdd(&g_cnt[r.z], 1);
    rk.w = atomicAdd(&g_cnt[r.w], 1);
    reinterpret_cast<int4*>(g_rank)[t] = rk;
}

// ---------------------------------------------------------------------------
// K3: single-pass exclusive scan of g_cnt -> g_rowptr (decoupled lookback).
// 98 blocks, all co-resident on 148 SMs -> spin-wait is deadlock-free.
// ---------------------------------------------------------------------------
__global__ void scan_lookback_kernel() {
    __shared__ int s[SCAN_BLK];
    __shared__ int base_sh;
    int tid = threadIdx.x;
    int b = blockIdx.x;
    int i = b * SCAN_BLK + tid;
    int v = (i < NN) ? g_cnt[i] : 0;
    s[tid] = v;
    __syncthreads();
#pragma unroll
    for (int off = 1; off < SCAN_BLK; off <<= 1) {
        int add = (tid >= off) ? s[tid - off] : 0;
        __syncthreads();
        s[tid] += add;
        __syncthreads();
    }
    if (tid == 0) {
        unsigned long long st = (1ull << 32) | (unsigned)s[SCAN_BLK - 1];
        atomicExch(&g_scanstate[b], st);
    }
    if (tid < 32) {
        int base = 0;
        for (int p = tid; p < b; p += 32) {
            unsigned long long st;
            do {
                st = *(volatile unsigned long long*)&g_scanstate[p];
            } while (!(st >> 32));
            base += (int)(st & 0xffffffffu);
        }
#pragma unroll
        for (int o = 16; o; o >>= 1)
            base += __shfl_down_sync(0xffffffffu, base, o);
        if (tid == 0) base_sh = base;
    }
    __syncthreads();
    if (i < NN) g_rowptr[i] = base_sh + s[tid] - v;   // exclusive
    if (i == 0) g_rowptr[NN] = EE;
}

// ---------------------------------------------------------------------------
// K4: scatter edges into CSR order (no atomics).  4 edges/thread (MLP=4).
// ---------------------------------------------------------------------------
__global__ void scatter_kernel(const int* __restrict__ rows,
                               const int* __restrict__ cols,
                               const float* __restrict__ vals) {
    int t = blockIdx.x * blockDim.x + threadIdx.x;   // over EE/4
    if (t >= EE / 4) return;
    int4   r  = reinterpret_cast<const int4*>(rows)[t];
    int4   rk = reinterpret_cast<const int4*>(g_rank)[t];
    int4   c  = reinterpret_cast<const int4*>(cols)[t];
    float4 v  = reinterpret_cast<const float4*>(vals)[t];
    // 4 independent rowptr gathers in flight
    int p0 = g_rowptr[r.x] + rk.x;
    int p1 = g_rowptr[r.y] + rk.y;
    int p2 = g_rowptr[r.z] + rk.z;
    int p3 = g_rowptr[r.w] + rk.w;
    g_cv[p0] = make_uint2((unsigned)c.x, __float_as_uint(v.x));
    g_cv[p1] = make_uint2((unsigned)c.y, __float_as_uint(v.y));
    g_cv[p2] = make_uint2((unsigned)c.z, __float_as_uint(v.z));
    g_cv[p3] = make_uint2((unsigned)c.w, __float_as_uint(v.w));
}

// ---------------------------------------------------------------------------
// K5/K6: CSR SpMM, warp per row. Edge metadata via warp-uniform broadcast
// loads (no shfl), 8 gathers in flight, fp16 gathers, fp32 accumulation.
//   MODE 0: gather g_a; acc = h1.  Epilogue: out = (emb[x[row]] + acc)/3,
//           g_b = half(dropout(acc, u2)).
//   MODE 1: gather g_b; acc = h2.  Epilogue: out += acc/3.
// ---------------------------------------------------------------------------
__device__ __forceinline__ void fma_h4(float4& acc, float v, uint2 m) {
    __half2 p0 = *reinterpret_cast<__half2*>(&m.x);
    __half2 p1 = *reinterpret_cast<__half2*>(&m.y);
    float2 f0 = __half22float2(p0);
    float2 f1 = __half22float2(p1);
    acc.x += v * f0.x; acc.y += v * f0.y;
    acc.z += v * f1.x; acc.w += v * f1.y;
}

template <int MODE>
__global__ void spmm_csr_kernel(const int* __restrict__ x,
                                const float* __restrict__ emb,
                                const float* __restrict__ u2,
                                float* __restrict__ out) {
    int gw   = (blockIdx.x * blockDim.x + threadIdx.x) >> 5;  // row
    int lane = threadIdx.x & 31;
    if (gw >= NN) return;

    int s = g_rowptr[gw];
    int e = g_rowptr[gw + 1];
    const uint2* __restrict__ cvp = g_cv;
    const uint2* __restrict__ gsrc =
        reinterpret_cast<const uint2*>(MODE == 0 ? g_ga : g_gb);

    float4 acc = make_float4(0.f, 0.f, 0.f, 0.f);

    int j = s;
    for (; j + 8 <= e; j += 8) {
        uint2 cv[8];
#pragma unroll
        for (int k = 0; k < 8; k++) cv[k] = cvp[j + k];      // uniform bcast
        uint2 m[8];
#pragma unroll
        for (int k = 0; k < 8; k++) m[k] = gsrc[(int)cv[k].x * 32 + lane];
#pragma unroll
        for (int k = 0; k < 8; k++)
            fma_h4(acc, __uint_as_float(cv[k].y), m[k]);
    }
    if (j + 4 <= e) {
        uint2 cv[4];
#pragma unroll
        for (int k = 0; k < 4; k++) cv[k] = cvp[j + k];
        uint2 m[4];
#pragma unroll
        for (int k = 0; k < 4; k++) m[k] = gsrc[(int)cv[k].x * 32 + lane];
#pragma unroll
        for (int k = 0; k < 4; k++)
            fma_h4(acc, __uint_as_float(cv[k].y), m[k]);
        j += 4;
    }
    for (; j < e; j++) {
        uint2 c = cvp[j];
        uint2 m = gsrc[(int)c.x * 32 + lane];
        fma_h4(acc, __uint_as_float(c.y), m);
    }

    int t = gw * 32 + lane;
    const float kk = 1.0f / 3.0f;
    if (MODE == 0) {
        // g_b = half(dropout(h1, u2))
        float4 u = reinterpret_cast<const float4*>(u2)[t];
        float gx  = (u.x >= RATE) ? acc.x * INV_KEEP : 0.f;
        float gy  = (u.y >= RATE) ? acc.y * INV_KEEP : 0.f;
        float gz  = (u.z >= RATE) ? acc.z * INV_KEEP : 0.f;
        float gw4 = (u.w >= RATE) ? acc.w * INV_KEEP : 0.f;
        __half2 p0 = __floats2half2_rn(gx, gy);
        __half2 p1 = __floats2half2_rn(gz, gw4);
        uint2 packed = make_uint2(*reinterpret_cast<unsigned*>(&p0),
                                  *reinterpret_cast<unsigned*>(&p1));
        reinterpret_cast<uint2*>(g_gb)[t] = packed;
        // out = (h0 + h1) / 3   (h0 read straight from emb)
        int xi = x[gw];                                  // warp-uniform
        float4 h = reinterpret_cast<const float4*>(emb + (size_t)xi * DD)[lane];
        float4 o;
        o.x = (h.x + acc.x) * kk;
        o.y = (h.y + acc.y) * kk;
        o.z = (h.z + acc.z) * kk;
        o.w = (h.w + acc.w) * kk;
        reinterpret_cast<float4*>(out)[t] = o;
    } else {
        // out += h2 / 3
        float4 p = reinterpret_cast<const float4*>(out)[t];
        float4 o;
        o.x = p.x + acc.x * kk;
        o.y = p.y + acc.y * kk;
        o.z = p.z + acc.z * kk;
        o.w = p.w + acc.w * kk;
        reinterpret_cast<float4*>(out)[t] = o;
    }
}

// ---------------------------------------------------------------------------
// kernel_launch — graph-capturable pipeline (6 launches)
// inputs: 0:x(int32)[N] 1:rows[E] 2:cols[E] 3:A_vals[E] 4:emb[N*D] 5:u1 6:u2
// ---------------------------------------------------------------------------
extern "C" void kernel_launch(void* const* d_in, const int* in_sizes, int n_in,
                              void* d_out, int out_size) {
    const int*   x    = (const int*)  d_in[0];
    const int*   rows = (const int*)  d_in[1];
    const int*   cols = (const int*)  d_in[2];
    const float* vals = (const float*)d_in[3];
    const float* emb  = (const float*)d_in[4];
    const float* u1   = (const float*)d_in[5];
    const float* u2   = (const float*)d_in[6];
    float* out = (float*)d_out;

    const int TPB = 256;
    const int nd4_blocks  = (NN * (DD / 4) + TPB - 1) / TPB;  // 12500
    const int e4_blocks   = (EE / 4 + TPB - 1) / TPB;         // 1563
    const int spmm_blocks = (NN * 32 + TPB - 1) / TPB;        // 12500

    embed_dropout_kernel<<<nd4_blocks, TPB>>>(x, emb, u1);    // + cnt/state reset
    hist_rank_kernel<<<e4_blocks, TPB>>>(rows);
    scan_lookback_kernel<<<SCAN_GRID, SCAN_BLK>>>();
    scatter_kernel<<<e4_blocks, TPB>>>(rows, cols, vals);

    spmm_csr_kernel<0><<<spmm_blocks, TPB>>>(x, emb, u2, out);
    spmm_csr_kernel<1><<<spmm_blocks, TPB>>>(x, emb, u2, out);
}

// round 17
// speedup vs baseline: 1.0199x; 1.0108x over previous
#include <cuda_runtime.h>
#include <cuda_fp16.h>
#include <cstdint>

// LightGCN_2: N=100000 nodes, D=128 channels, E=1600000 edges
#define NN 100000
#define DD 128
#define EE 1600000
#define RATE 0.1f
#define INV_KEEP (1.0f / 0.9f)

#define SCAN_BLK 1024
#define SCAN_GRID ((NN + SCAN_BLK - 1) / SCAN_BLK)   // 98

// ---------------------------------------------------------------------------
// Static device scratch (allocation-free rule: __device__ globals)
// ---------------------------------------------------------------------------
__device__ __align__(16) float  g_h1[NN * DD];      // layer-1 output  (fp32) [kept for clarity; unused]
__device__ __align__(16) __half g_ga[NN * DD];      // dropout(h0,u1)  (fp16)
__device__ __align__(16) __half g_gb[NN * DD];      // dropout(h1,u2)  (fp16)

__device__ __align__(16) uint2 g_cv[EE];            // CSR payload {col, val bits}
__device__ __align__(16) int g_rank[EE];            // arrival rank within row
__device__ int g_cnt[NN];                           // row histogram
__device__ int g_rowptr[NN + 1];                    // CSR row pointers
__device__ unsigned long long g_scanstate[SCAN_GRID]; // lookback: hi32=ready, lo32=total

// ---------------------------------------------------------------------------
// K1: g_a = half(dropout(emb[x], u1)); also resets cnt + scan state.
// (h0 is NOT materialized — SpMM-0's epilogue re-reads emb directly.)
// ---------------------------------------------------------------------------
__global__ void embed_dropout_kernel(const int* __restrict__ x,
                                     const float* __restrict__ emb,
                                     const float* __restrict__ u1) {
    int t = blockIdx.x * blockDim.x + threadIdx.x;   // over N*32
    if (t < NN) g_cnt[t] = 0;
    if (t < SCAN_GRID) g_scanstate[t] = 0ull;
    if (t >= NN * (DD / 4)) return;
    int i = t >> 5;
    int q = t & 31;
    int xi = x[i];
    float4 h = reinterpret_cast<const float4*>(emb + (size_t)xi * DD)[q];
    float4 u = reinterpret_cast<const float4*>(u1)[t];
    float gx = (u.x >= RATE) ? h.x * INV_KEEP : 0.f;
    float gy = (u.y >= RATE) ? h.y * INV_KEEP : 0.f;
    float gz = (u.z >= RATE) ? h.z * INV_KEEP : 0.f;
    float gw = (u.w >= RATE) ? h.w * INV_KEEP : 0.f;
    __half2 p0 = __floats2half2_rn(gx, gy);
    __half2 p1 = __floats2half2_rn(gz, gw);
    uint2 packed = make_uint2(*reinterpret_cast<unsigned*>(&p0),
                              *reinterpret_cast<unsigned*>(&p1));
    reinterpret_cast<uint2*>(g_ga)[t] = packed;
}

// ---------------------------------------------------------------------------
// K2: histogram + per-edge arrival rank.  4 edges/thread (MLP=4).
// ---------------------------------------------------------------------------
__global__ void hist_rank_kernel(const int* __restrict__ rows) {
    int t = blockIdx.x * blockDim.x + threadIdx.x;   // over EE/4
    if (t >= EE / 4) return;
    int4 r = reinterpret_cast<const int4*>(rows)[t];
    int4 rk;
    rk.x = atomicAdd(&g_cnt[r.x], 1);
    rk.y = atomicAdd(&g_cnt[r.y], 1);
    rk.z = atomicAdd(&g_cnt[r.z], 1);
    rk.w = atomicAdd(&g_cnt[r.w], 1);
    reinterpret_cast<int4*>(g_rank)[t] = rk;
}

// ---------------------------------------------------------------------------
// K3: single-pass exclusive scan of g_cnt -> g_rowptr (decoupled lookback).
// 98 blocks, all co-resident on 148 SMs -> spin-wait is deadlock-free.
// ---------------------------------------------------------------------------
__global__ void scan_lookback_kernel() {
    __shared__ int s[SCAN_BLK];
    __shared__ int base_sh;
    int tid = threadIdx.x;
    int b = blockIdx.x;
    int i = b * SCAN_BLK + tid;
    int v = (i < NN) ? g_cnt[i] : 0;
    s[tid] = v;
    __syncthreads();
#pragma unroll
    for (int off = 1; off < SCAN_BLK; off <<= 1) {
        int add = (tid >= off) ? s[tid - off] : 0;
        __syncthreads();
        s[tid] += add;
        __syncthreads();
    }
    if (tid == 0) {
        unsigned long long st = (1ull << 32) | (unsigned)s[SCAN_BLK - 1];
        atomicExch(&g_scanstate[b], st);
    }
    if (tid < 32) {
        int base = 0;
        for (int p = tid; p < b; p += 32) {
            unsigned long long st;
            do {
                st = *(volatile unsigned long long*)&g_scanstate[p];
            } while (!(st >> 32));
            base += (int)(st & 0xffffffffu);
        }
#pragma unroll
        for (int o = 16; o; o >>= 1)
            base += __shfl_down_sync(0xffffffffu, base, o);
        if (tid == 0) base_sh = base;
    }
    __syncthreads();
    if (i < NN) g_rowptr[i] = base_sh + s[tid] - v;   // exclusive
    if (i == 0) g_rowptr[NN] = EE;
}

// ---------------------------------------------------------------------------
// K4: scatter edges into CSR order (no atomics).  4 edges/thread (MLP=4).
// ---------------------------------------------------------------------------
__global__ void scatter_kernel(const int* __restrict__ rows,
                               const int* __restrict__ cols,
                               const float* __restrict__ vals) {
    int t = blockIdx.x * blockDim.x + threadIdx.x;   // over EE/4
    if (t >= EE / 4) return;
    int4   r  = reinterpret_cast<const int4*>(rows)[t];
    int4   rk = reinterpret_cast<const int4*>(g_rank)[t];
    int4   c  = reinterpret_cast<const int4*>(cols)[t];
    float4 v  = reinterpret_cast<const float4*>(vals)[t];
    // 4 independent rowptr gathers in flight
    int p0 = g_rowptr[r.x] + rk.x;
    int p1 = g_rowptr[r.y] + rk.y;
    int p2 = g_rowptr[r.z] + rk.z;
    int p3 = g_rowptr[r.w] + rk.w;
    g_cv[p0] = make_uint2((unsigned)c.x, __float_as_uint(v.x));
    g_cv[p1] = make_uint2((unsigned)c.y, __float_as_uint(v.y));
    g_cv[p2] = make_uint2((unsigned)c.z, __float_as_uint(v.z));
    g_cv[p3] = make_uint2((unsigned)c.w, __float_as_uint(v.w));
}

// ---------------------------------------------------------------------------
// K5/K6: CSR SpMM, warp per row. Edge metadata via warp-uniform broadcast
// loads (no shfl), 8 gathers in flight, fp16 gathers, fp32 accumulation.
//   MODE 0: gather g_a; acc = h1.  Epilogue: out = (emb[x[row]] + acc)/3,
//           g_b = half(dropout(acc, u2)).
//   MODE 1: gather g_b; acc = h2.  Epilogue: out += acc/3.
// ---------------------------------------------------------------------------
__device__ __forceinline__ void fma_h4(float4& acc, float v, uint2 m) {
    __half2 p0 = *reinterpret_cast<__half2*>(&m.x);
    __half2 p1 = *reinterpret_cast<__half2*>(&m.y);
    float2 f0 = __half22float2(p0);
    float2 f1 = __half22float2(p1);
    acc.x += v * f0.x; acc.y += v * f0.y;
    acc.z += v * f1.x; acc.w += v * f1.y;
}

template <int MODE>
__global__ void spmm_csr_kernel(const int* __restrict__ x,
                                const float* __restrict__ emb,
                                const float* __restrict__ u2,
                                float* __restrict__ out) {
    int gw   = (blockIdx.x * blockDim.x + threadIdx.x) >> 5;  // row
    int lane = threadIdx.x & 31;
    if (gw >= NN) return;

    int s = g_rowptr[gw];
    int e = g_rowptr[gw + 1];
    const uint2* __restrict__ cvp = g_cv;
    const uint2* __restrict__ gsrc =
        reinterpret_cast<const uint2*>(MODE == 0 ? g_ga : g_gb);

    float4 acc = make_float4(0.f, 0.f, 0.f, 0.f);

    int j = s;
    for (; j + 8 <= e; j += 8) {
        uint2 cv[8];
#pragma unroll
        for (int k = 0; k < 8; k++) cv[k] = cvp[j + k];      // uniform bcast
        uint2 m[8];
#pragma unroll
        for (int k = 0; k < 8; k++) m[k] = gsrc[(int)cv[k].x * 32 + lane];
#pragma unroll
        for (int k = 0; k < 8; k++)
            fma_h4(acc, __uint_as_float(cv[k].y), m[k]);
    }
    if (j + 4 <= e) {
        uint2 cv[4];
#pragma unroll
        for (int k = 0; k < 4; k++) cv[k] = cvp[j + k];
        uint2 m[4];
#pragma unroll
        for (int k = 0; k < 4; k++) m[k] = gsrc[(int)cv[k].x * 32 + lane];
#pragma unroll
        for (int k = 0; k < 4; k++)
            fma_h4(acc, __uint_as_float(cv[k].y), m[k]);
        j += 4;
    }
    for (; j < e; j++) {
        uint2 c = cvp[j];
        uint2 m = gsrc[(int)c.x * 32 + lane];
        fma_h4(acc, __uint_as_float(c.y), m);
    }

    int t = gw * 32 + lane;
    const float kk = 1.0f / 3.0f;
    if (MODE == 0) {
        // g_b = half(dropout(h1, u2))
        float4 u = reinterpret_cast<const float4*>(u2)[t];
        float gx  = (u.x >= RATE) ? acc.x * INV_KEEP : 0.f;
        float gy  = (u.y >= RATE) ? acc.y * INV_KEEP : 0.f;
        float gz  = (u.z >= RATE) ? acc.z * INV_KEEP : 0.f;
        float gw4 = (u.w >= RATE) ? acc.w * INV_KEEP : 0.f;
        __half2 p0 = __floats2half2_rn(gx, gy);
        __half2 p1 = __floats2half2_rn(gz, gw4);
        uint2 packed = make_uint2(*reinterpret_cast<unsigned*>(&p0),
                                  *reinterpret_cast<unsigned*>(&p1));
        reinterpret_cast<uint2*>(g_gb)[t] = packed;
        // out = (h0 + h1) / 3   (h0 read straight from emb)
        int xi = x[gw];                                  // warp-uniform
        float4 h = reinterpret_cast<const float4*>(emb + (size_t)xi * DD)[lane];
        float4 o;
        o.x = (h.x + acc.x) * kk;
        o.y = (h.y + acc.y) * kk;
        o.z = (h.z + acc.z) * kk;
        o.w = (h.w + acc.w) * kk;
        reinterpret_cast<float4*>(out)[t] = o;
    } else {
        // out += h2 / 3
        float4 p = reinterpret_cast<const float4*>(out)[t];
        float4 o;
        o.x = p.x + acc.x * kk;
        o.y = p.y + acc.y * kk;
        o.z = p.z + acc.z * kk;
        o.w = p.w + acc.w * kk;
        reinterpret_cast<float4*>(out)[t] = o;
    }
}

// ---------------------------------------------------------------------------
// kernel_launch — graph-capturable pipeline (6 launches)
// inputs: 0:x(int32)[N] 1:rows[E] 2:cols[E] 3:A_vals[E] 4:emb[N*D] 5:u1 6:u2
// ---------------------------------------------------------------------------
extern "C" void kernel_launch(void* const* d_in, const int* in_sizes, int n_in,
                              void* d_out, int out_size) {
    const int*   x    = (const int*)  d_in[0];
    const int*   rows = (const int*)  d_in[1];
    const int*   cols = (const int*)  d_in[2];
    const float* vals = (const float*)d_in[3];
    const float* emb  = (const float*)d_in[4];
    const float* u1   = (const float*)d_in[5];
    const float* u2   = (const float*)d_in[6];
    float* out = (float*)d_out;

    const int TPB = 256;
    const int nd4_blocks  = (NN * (DD / 4) + TPB - 1) / TPB;  // 12500
    const int e4_blocks   = (EE / 4 + TPB - 1) / TPB;         // 1563
    const int spmm_blocks = (NN * 32 + TPB - 1) / TPB;        // 12500

    embed_dropout_kernel<<<nd4_blocks, TPB>>>(x, emb, u1);    // + cnt/state reset
    hist_rank_kernel<<<e4_blocks, TPB>>>(rows);
    scan_lookback_kernel<<<SCAN_GRID, SCAN_BLK>>>();
    scatter_kernel<<<e4_blocks, TPB>>>(rows, cols, vals);

    spmm_csr_kernel<0><<<spmm_blocks, TPB>>>(x, emb, u2, out);
    spmm_csr_kernel<1><<<spmm_blocks, TPB>>>(x, emb, u2, out);
}